// round 7
// baseline (speedup 1.0000x reference)
#include <cuda_runtime.h>
#include <cuda_bf16.h>
#include <math.h>
#include <stdint.h>

// ---------------- problem constants (fixed instance) ----------------
#define NN   100000
#define FIN  512
#define C1   64          // heads1*out1 = 8*8
#define H1   8
#define EE   1600000
#define ET   (EE + NN)   // edges + self loops
#define C2   40
#define NEG  0.2f
#define NBLK 98          // scan blocks: ceil(NN/1024)

// ---------------- static device scratch (no allocs allowed) ----------------
__device__ float g_h1[NN * C1];
__device__ float g_als1[NN * H1];
__device__ float g_ald1[NN * H1];
__device__ float g_out1[NN * C1];
__device__ float g_h2[NN * C2];
__device__ float g_als2[NN];
__device__ float g_ald2[NN];
__device__ int   g_cnt[NN];
__device__ int   g_rowptr[NN + 1];
__device__ int   g_cursor[NN];
__device__ int   g_col[ET];
__device__ int   g_blksum[NBLK];
__device__ int   g_blkoff[NBLK];
__device__ __nv_bfloat16 g_W1hT[C1 * FIN];   // [n][k] transposed hi
__device__ __nv_bfloat16 g_W1lT[C1 * FIN];   // [n][k] transposed lo

__device__ __forceinline__ float lrelu(float x) { return x > 0.f ? x : NEG * x; }

__device__ __forceinline__ uint32_t smem_u32(const void* p) {
    return (uint32_t)__cvta_generic_to_shared(p);
}
// pack two f32 -> bf16x2, lo half = a (even k), hi half = b (odd k)
__device__ __forceinline__ uint32_t bf16x2(float a, float b) {
    uint32_t r;
    asm("cvt.rn.bf16x2.f32 %0, %1, %2;" : "=r"(r) : "f"(b), "f"(a));
    return r;
}

#define LDSM4(r0, r1, r2, r3, addr)                                            \
    asm volatile("ldmatrix.sync.aligned.m8n8.x4.shared.b16 {%0,%1,%2,%3},[%4];"\
                 : "=r"(r0), "=r"(r1), "=r"(r2), "=r"(r3) : "r"(addr))

#define MMA_BF16(d, a, b0, b1)                                                 \
    asm volatile(                                                              \
        "mma.sync.aligned.m16n8k16.row.col.f32.bf16.bf16.f32 "                 \
        "{%0,%1,%2,%3},{%4,%5,%6,%7},{%8,%9},{%0,%1,%2,%3};"                   \
        : "+f"(d[0]), "+f"(d[1]), "+f"(d[2]), "+f"(d[3])                       \
        : "r"(a[0]), "r"(a[1]), "r"(a[2]), "r"(a[3]), "r"(b0), "r"(b1))

#define CP_ASYNC16(dst, src)                                                   \
    asm volatile("cp.async.ca.shared.global [%0], [%1], 16;" ::                \
                 "r"(dst), "l"(src))

// =====================================================================
// prep: split W1 into bf16 hi/lo, transposed to [n][k]
// =====================================================================
__global__ void k_prepw(const float* __restrict__ W) {
    int i = blockIdx.x * blockDim.x + threadIdx.x;
    if (i < FIN * C1) {
        int k = i >> 6, n = i & 63;
        float w = W[i];
        __nv_bfloat16 hi = __float2bfloat16(w);
        __nv_bfloat16 lo = __float2bfloat16(w - __bfloat162float(hi));
        g_W1hT[n * FIN + k] = hi;
        g_W1lT[n * FIN + k] = lo;
    }
}

// =====================================================================
// GEMM1: bf16 split-MMA, M=128 x N=64 tile, KC=32, 8 warps (m16 each).
// Fused logits1 in epilogue.
// =====================================================================
__global__ __launch_bounds__(256) void k_gemm1_tc(const float* __restrict__ x,
                                                  const float* __restrict__ as1,
                                                  const float* __restrict__ ad1) {
    __shared__ uint32_t Ah[128][20];      // bf16x2 words, row stride 80B
    __shared__ uint32_t Al[128][20];
    __shared__ uint32_t Bh[2][64][20];    // [buf][n][kwords]
    __shared__ uint32_t Bl[2][64][20];

    const int tid  = threadIdx.x;
    const int warp = tid >> 5;
    const int lane = tid & 31;
    const int r0   = blockIdx.x * 128;
    const int mrow = warp * 16;

    // ---- A global load mapping: thread -> (row, 16 k) ----
    const int arow = tid >> 1;
    const int kb   = (tid & 1) * 16;
    int gr = r0 + arow;
    if (gr >= NN) gr = NN - 1;
    const float* xp = x + (size_t)gr * FIN + kb;

    // ---- B cp.async mapping: thread -> (n, 8 k) ----
    const int bn = tid >> 2;
    const int bw = tid & 3;
    const __nv_bfloat16* whp = g_W1hT + bn * FIN + bw * 8;
    const __nv_bfloat16* wlp = g_W1lT + bn * FIN + bw * 8;

    // ---- ldmatrix lane address offsets ----
    const int a_m  = mrow + (lane & 7) + ((lane >> 3) & 1) * 8;
    const int a_kw = (lane >> 4) * 4;        // k half in words
    const uint32_t aAddrH = smem_u32(&Ah[a_m][a_kw]);
    const uint32_t aAddrL = smem_u32(&Al[a_m][a_kw]);

    const int bmat = lane >> 3;
    uint32_t bOff[4];
#pragma unroll
    for (int p = 0; p < 4; p++) {
        int n = p * 16 + (bmat >> 1) * 8 + (lane & 7);
        bOff[p] = (uint32_t)((n * 20 + (bmat & 1) * 4) * 4);   // bytes
    }
    const uint32_t bBaseH0 = smem_u32(&Bh[0][0][0]);
    const uint32_t bBaseL0 = smem_u32(&Bl[0][0][0]);
    const uint32_t bufStride = (uint32_t)(64 * 20 * 4);

    float acc[8][4];
#pragma unroll
    for (int nb = 0; nb < 8; nb++)
#pragma unroll
        for (int i = 0; i < 4; i++) acc[nb][i] = 0.f;

    // ---- prologue: A regs tile0, cp.async B tile0 ----
    float4 v0 = *(const float4*)(xp + 0);
    float4 v1 = *(const float4*)(xp + 4);
    float4 v2 = *(const float4*)(xp + 8);
    float4 v3 = *(const float4*)(xp + 12);
    {
        uint32_t dh = smem_u32(&Bh[0][bn][bw * 4]);
        uint32_t dl = smem_u32(&Bl[0][bn][bw * 4]);
        CP_ASYNC16(dh, whp);
        CP_ASYNC16(dl, wlp);
        asm volatile("cp.async.commit_group;");
    }

    const int awords = kb >> 1;           // 0 or 8
    for (int t = 0; t < 16; t++) {
        // convert + store A tile
        {
            uint32_t w0 = bf16x2(v0.x, v0.y);
            uint32_t w1 = bf16x2(v0.z, v0.w);
            uint32_t w2 = bf16x2(v1.x, v1.y);
            uint32_t w3 = bf16x2(v1.z, v1.w);
            uint32_t w4 = bf16x2(v2.x, v2.y);
            uint32_t w5 = bf16x2(v2.z, v2.w);
            uint32_t w6 = bf16x2(v3.x, v3.y);
            uint32_t w7 = bf16x2(v3.z, v3.w);
            uint32_t l0 = bf16x2(v0.x - __uint_as_float(w0 << 16), v0.y - __uint_as_float(w0 & 0xffff0000u));
            uint32_t l1 = bf16x2(v0.z - __uint_as_float(w1 << 16), v0.w - __uint_as_float(w1 & 0xffff0000u));
            uint32_t l2 = bf16x2(v1.x - __uint_as_float(w2 << 16), v1.y - __uint_as_float(w2 & 0xffff0000u));
            uint32_t l3 = bf16x2(v1.z - __uint_as_float(w3 << 16), v1.w - __uint_as_float(w3 & 0xffff0000u));
            uint32_t l4 = bf16x2(v2.x - __uint_as_float(w4 << 16), v2.y - __uint_as_float(w4 & 0xffff0000u));
            uint32_t l5 = bf16x2(v2.z - __uint_as_float(w5 << 16), v2.w - __uint_as_float(w5 & 0xffff0000u));
            uint32_t l6 = bf16x2(v3.x - __uint_as_float(w6 << 16), v3.y - __uint_as_float(w6 & 0xffff0000u));
            uint32_t l7 = bf16x2(v3.z - __uint_as_float(w7 << 16), v3.w - __uint_as_float(w7 & 0xffff0000u));
            *(uint4*)&Ah[arow][awords]     = make_uint4(w0, w1, w2, w3);
            *(uint4*)&Ah[arow][awords + 4] = make_uint4(w4, w5, w6, w7);
            *(uint4*)&Al[arow][awords]     = make_uint4(l0, l1, l2, l3);
            *(uint4*)&Al[arow][awords + 4] = make_uint4(l4, l5, l6, l7);
        }
        if (t < 15) {
            int nb2 = (t + 1) & 1;
            uint32_t dh = smem_u32(&Bh[nb2][bn][bw * 4]);
            uint32_t dl = smem_u32(&Bl[nb2][bn][bw * 4]);
            const __nv_bfloat16* sh = whp + (t + 1) * 32;
            const __nv_bfloat16* sl = wlp + (t + 1) * 32;
            CP_ASYNC16(dh, sh);
            CP_ASYNC16(dl, sl);
            asm volatile("cp.async.commit_group;");
            asm volatile("cp.async.wait_group 1;");
        } else {
            asm volatile("cp.async.wait_group 0;");
        }
        __syncthreads();
        if (t < 15) {
            const float* nxp = xp + (t + 1) * 32;
            v0 = *(const float4*)(nxp + 0);
            v1 = *(const float4*)(nxp + 4);
            v2 = *(const float4*)(nxp + 8);
            v3 = *(const float4*)(nxp + 12);
        }
        const uint32_t bh = bBaseH0 + (t & 1) * bufStride;
        const uint32_t bl = bBaseL0 + (t & 1) * bufStride;
#pragma unroll
        for (int s = 0; s < 2; s++) {
            uint32_t ah[4], al[4];
            LDSM4(ah[0], ah[1], ah[2], ah[3], aAddrH + s * 32);
            LDSM4(al[0], al[1], al[2], al[3], aAddrL + s * 32);
#pragma unroll
            for (int p = 0; p < 4; p++) {
                uint32_t h0, h1, h2, h3, q0, q1, q2, q3;
                LDSM4(h0, h1, h2, h3, bh + bOff[p] + s * 32);
                LDSM4(q0, q1, q2, q3, bl + bOff[p] + s * 32);
                MMA_BF16(acc[2 * p],     ah, h0, h1);
                MMA_BF16(acc[2 * p],     al, h0, h1);
                MMA_BF16(acc[2 * p],     ah, q0, q1);
                MMA_BF16(acc[2 * p + 1], ah, h2, h3);
                MMA_BF16(acc[2 * p + 1], al, h2, h3);
                MMA_BF16(acc[2 * p + 1], ah, q2, q3);
            }
        }
        __syncthreads();
    }

    // ---- epilogue: store h1 + fused per-head logits ----
    const int q  = lane & 3;
    const int g4 = lane >> 2;
    float sv[16], dv[16];
#pragma unroll
    for (int nb = 0; nb < 8; nb++) {
        sv[nb * 2]     = __ldg(as1 + nb * 8 + 2 * q);
        sv[nb * 2 + 1] = __ldg(as1 + nb * 8 + 2 * q + 1);
        dv[nb * 2]     = __ldg(ad1 + nb * 8 + 2 * q);
        dv[nb * 2 + 1] = __ldg(ad1 + nb * 8 + 2 * q + 1);
    }
#pragma unroll
    for (int half = 0; half < 2; half++) {
        int grw = r0 + mrow + g4 + half * 8;
        float hs[8], hd[8];
#pragma unroll
        for (int nb = 0; nb < 8; nb++) {
            float c0 = acc[nb][half * 2];
            float c1 = acc[nb][half * 2 + 1];
            hs[nb] = c0 * sv[nb * 2] + c1 * sv[nb * 2 + 1];
            hd[nb] = c0 * dv[nb * 2] + c1 * dv[nb * 2 + 1];
            if (grw < NN) {
                *(float2*)&g_h1[(size_t)grw * C1 + nb * 8 + 2 * q] = make_float2(c0, c1);
            }
        }
#pragma unroll
        for (int off = 1; off <= 2; off <<= 1) {
#pragma unroll
            for (int nb = 0; nb < 8; nb++) {
                hs[nb] += __shfl_xor_sync(0xffffffffu, hs[nb], off);
                hd[nb] += __shfl_xor_sync(0xffffffffu, hd[nb], off);
            }
        }
        if (q == 0 && grw < NN) {
            *(float4*)&g_als1[grw * H1]     = make_float4(hs[0], hs[1], hs[2], hs[3]);
            *(float4*)&g_als1[grw * H1 + 4] = make_float4(hs[4], hs[5], hs[6], hs[7]);
            *(float4*)&g_ald1[grw * H1]     = make_float4(hd[0], hd[1], hd[2], hd[3]);
            *(float4*)&g_ald1[grw * H1 + 4] = make_float4(hd[4], hd[5], hd[6], hd[7]);
        }
    }
}

// =====================================================================
// CSR build
// =====================================================================
__global__ void k_initcnt() {
    int i = blockIdx.x * blockDim.x + threadIdx.x;
    if (i < NN) g_cnt[i] = 1;
}

__global__ void k_hist(const int* __restrict__ ei) {
    int e = blockIdx.x * blockDim.x + threadIdx.x;
    if (e < EE) atomicAdd(&g_cnt[ei[EE + e]], 1);
}

__global__ __launch_bounds__(1024) void k_scanA() {
    __shared__ int wsum[32];
    const int t    = threadIdx.x;
    const int lane = t & 31;
    const int warp = t >> 5;
    const int idx  = blockIdx.x * 1024 + t;
    int v = (idx < NN) ? g_cnt[idx] : 0;
    int s = v;
#pragma unroll
    for (int off = 1; off < 32; off <<= 1) {
        int n = __shfl_up_sync(0xffffffffu, s, off);
        if (lane >= off) s += n;
    }
    if (lane == 31) wsum[warp] = s;
    __syncthreads();
    if (warp == 0) {
        int ws = wsum[lane];
#pragma unroll
        for (int off = 1; off < 32; off <<= 1) {
            int n = __shfl_up_sync(0xffffffffu, ws, off);
            if (lane >= off) ws += n;
        }
        wsum[lane] = ws;
    }
    __syncthreads();
    int incl = s + (warp > 0 ? wsum[warp - 1] : 0);
    if (idx < NN) g_rowptr[idx] = incl - v;
    if (t == 1023) g_blksum[blockIdx.x] = incl;
}

__global__ void k_scanB() {
    int run = 0;
    for (int b = 0; b < NBLK; b++) {
        g_blkoff[b] = run;
        run += g_blksum[b];
    }
    g_rowptr[NN] = run;
}

__global__ __launch_bounds__(1024) void k_scanC() {
    int idx = blockIdx.x * 1024 + threadIdx.x;
    if (idx < NN) {
        int r = g_rowptr[idx] + g_blkoff[idx >> 10];
        g_rowptr[idx] = r;
        g_cursor[idx] = r;
    }
}

__global__ void k_scatter(const int* __restrict__ ei) {
    int i = blockIdx.x * blockDim.x + threadIdx.x;
    if (i >= EE + NN) return;
    int s, d;
    if (i < EE) { s = ei[i]; d = ei[EE + i]; }
    else        { s = i - EE; d = s; }
    int p = atomicAdd(&g_cursor[d], 1);
    g_col[p] = s;
}

// =====================================================================
// agg1: warp per dst. Fast path for degree<=32.
// =====================================================================
__global__ __launch_bounds__(256) void k_agg1() {
    __shared__ float s_alpha[8][32 * 8];
    const int tid  = threadIdx.x;
    const int wid  = tid >> 5;
    const int lane = tid & 31;
    const int d    = blockIdx.x * 8 + wid;

    const int beg = g_rowptr[d];
    const int end = g_rowptr[d + 1];
    const int deg = end - beg;

    float4 ad0 = *(const float4*)&g_ald1[d * H1];
    float4 ad1 = *(const float4*)&g_ald1[d * H1 + 4];
    float ald[H1] = {ad0.x, ad0.y, ad0.z, ad0.w, ad1.x, ad1.y, ad1.z, ad1.w};

    float* sa = s_alpha[wid];
    const int c0 = lane, c1 = lane + 32;
    const int h0 = lane >> 3;
    float acc0 = 0.f, acc1 = 0.f;

    if (deg <= 32) {
        int k = beg + lane;
        bool act = k < end;
        int s = act ? g_col[k] : 0;
        float e[H1];
        if (act) {
            float4 a0 = *(const float4*)&g_als1[s * H1];
            float4 a1 = *(const float4*)&g_als1[s * H1 + 4];
            float av[H1] = {a0.x, a0.y, a0.z, a0.w, a1.x, a1.y, a1.z, a1.w};
#pragma unroll
            for (int h = 0; h < H1; h++) e[h] = lrelu(av[h] + ald[h]);
        } else {
#pragma unroll
            for (int h = 0; h < H1; h++) e[h] = -1e30f;
        }
        float m[H1], p[H1], den[H1];
#pragma unroll
        for (int h = 0; h < H1; h++) m[h] = e[h];
#pragma unroll
        for (int h = 0; h < H1; h++)
#pragma unroll
            for (int off = 16; off >= 1; off >>= 1)
                m[h] = fmaxf(m[h], __shfl_xor_sync(0xffffffffu, m[h], off));
#pragma unroll
        for (int h = 0; h < H1; h++) { p[h] = act ? __expf(e[h] - m[h]) : 0.f; den[h] = p[h]; }
#pragma unroll
        for (int h = 0; h < H1; h++)
#pragma unroll
            for (int off = 16; off >= 1; off >>= 1)
                den[h] += __shfl_xor_sync(0xffffffffu, den[h], off);
#pragma unroll
        for (int h = 0; h < H1; h++) p[h] *= (1.f / den[h]);

        *(float4*)&sa[lane * 8]     = make_float4(p[0], p[1], p[2], p[3]);
        *(float4*)&sa[lane * 8 + 4] = make_float4(p[4], p[5], p[6], p[7]);
        __syncwarp();
#pragma unroll 4
        for (int j = 0; j < deg; j++) {
            int sj = __shfl_sync(0xffffffffu, s, j);
            float a0 = sa[j * 8 + h0];
            float a1 = sa[j * 8 + h0 + 4];
            const float* hp = &g_h1[(size_t)sj * C1];
            acc0 = fmaf(__ldg(hp + c0), a0, acc0);
            acc1 = fmaf(__ldg(hp + c1), a1, acc1);
        }
    } else {
        float m[H1];
#pragma unroll
        for (int h = 0; h < H1; h++) m[h] = -1e30f;
        for (int k = beg + lane; k < end; k += 32) {
            int s = g_col[k];
            float4 a0 = *(const float4*)&g_als1[s * H1];
            float4 a1 = *(const float4*)&g_als1[s * H1 + 4];
            float av[H1] = {a0.x, a0.y, a0.z, a0.w, a1.x, a1.y, a1.z, a1.w};
#pragma unroll
            for (int h = 0; h < H1; h++) m[h] = fmaxf(m[h], lrelu(av[h] + ald[h]));
        }
#pragma unroll
        for (int h = 0; h < H1; h++)
#pragma unroll
            for (int off = 16; off >= 1; off >>= 1)
                m[h] = fmaxf(m[h], __shfl_xor_sync(0xffffffffu, m[h], off));

        float den[H1];
#pragma unroll
        for (int h = 0; h < H1; h++) den[h] = 0.f;
        for (int k = beg + lane; k < end; k += 32) {
            int s = g_col[k];
            float4 a0 = *(const float4*)&g_als1[s * H1];
            float4 a1 = *(const float4*)&g_als1[s * H1 + 4];
            float av[H1] = {a0.x, a0.y, a0.z, a0.w, a1.x, a1.y, a1.z, a1.w};
#pragma unroll
            for (int h = 0; h < H1; h++) den[h] += __expf(lrelu(av[h] + ald[h]) - m[h]);
        }
#pragma unroll
        for (int h = 0; h < H1; h++)
#pragma unroll
            for (int off = 16; off >= 1; off >>= 1)
                den[h] += __shfl_xor_sync(0xffffffffu, den[h], off);
        float inv[H1];
#pragma unroll
        for (int h = 0; h < H1; h++) inv[h] = 1.f / den[h];

        for (int base = beg; base < end; base += 32) {
            int k = base + lane;
            int s = 0;
            float al[H1];
#pragma unroll
            for (int h = 0; h < H1; h++) al[h] = 0.f;
            if (k < end) {
                s = g_col[k];
                float4 a0 = *(const float4*)&g_als1[s * H1];
                float4 a1 = *(const float4*)&g_als1[s * H1 + 4];
                float av[H1] = {a0.x, a0.y, a0.z, a0.w, a1.x, a1.y, a1.z, a1.w};
#pragma unroll
                for (int h = 0; h < H1; h++)
                    al[h] = __expf(lrelu(av[h] + ald[h]) - m[h]) * inv[h];
            }
            *(float4*)&sa[lane * 8]     = make_float4(al[0], al[1], al[2], al[3]);
            *(float4*)&sa[lane * 8 + 4] = make_float4(al[4], al[5], al[6], al[7]);
            __syncwarp();
            int cnt = min(32, end - base);
#pragma unroll 4
            for (int j = 0; j < cnt; j++) {
                int sj = __shfl_sync(0xffffffffu, s, j);
                float a0 = sa[j * 8 + h0];
                float a1 = sa[j * 8 + h0 + 4];
                const float* hp = &g_h1[(size_t)sj * C1];
                acc0 = fmaf(__ldg(hp + c0), a0, acc0);
                acc1 = fmaf(__ldg(hp + c1), a1, acc1);
            }
            __syncwarp();
        }
    }
    g_out1[(size_t)d * C1 + c0] = acc0;
    g_out1[(size_t)d * C1 + c1] = acc1;
}

// =====================================================================
// GEMM2 fused: h2 = lrelu(out1 + b1) @ W2 ; also logits2
// =====================================================================
__global__ __launch_bounds__(256) void k_gemm2(const float* __restrict__ b1,
                                               const float* __restrict__ W2,
                                               const float* __restrict__ att_s,
                                               const float* __restrict__ att_d) {
    __shared__ float As[64][65];
    __shared__ float Ws[64][C2];
    __shared__ float sb1[64], s_as[C2], s_ad[C2];
    const int tid = threadIdx.x;
    if (tid < 64) sb1[tid] = b1[tid];
    if (tid < C2) { s_as[tid] = att_s[tid]; s_ad[tid] = att_d[tid]; }
    __syncthreads();

    const int r0 = blockIdx.x * 64;
    for (int i = tid; i < 64 * C2; i += 256) Ws[i / C2][i % C2] = W2[i];
#pragma unroll
    for (int it = 0; it < 4; it++) {
        int idx  = tid + it * 256;
        int row  = idx >> 4;
        int c4   = (idx & 15) * 4;
        int grow = r0 + row;
        if (grow >= NN) grow = NN - 1;
        float4 v = *(const float4*)&g_out1[(size_t)grow * C1 + c4];
        As[row][c4 + 0] = lrelu(v.x + sb1[c4 + 0]);
        As[row][c4 + 1] = lrelu(v.y + sb1[c4 + 1]);
        As[row][c4 + 2] = lrelu(v.z + sb1[c4 + 2]);
        As[row][c4 + 3] = lrelu(v.w + sb1[c4 + 3]);
    }
    __syncthreads();

    const int tx = tid & 7;
    const int tn = tid >> 3;
    float acc[2][5];
#pragma unroll
    for (int h = 0; h < 2; h++)
#pragma unroll
        for (int j = 0; j < 5; j++) acc[h][j] = 0.f;

#pragma unroll 4
    for (int k = 0; k < 64; k++) {
        float a0 = As[tn][k];
        float a1 = As[tn + 32][k];
#pragma unroll
        for (int j = 0; j < 5; j++) {
            float w = Ws[k][tx * 5 + j];
            acc[0][j] = fmaf(a0, w, acc[0][j]);
            acc[1][j] = fmaf(a1, w, acc[1][j]);
        }
    }
#pragma unroll
    for (int half = 0; half < 2; half++) {
        int grow = r0 + tn + half * 32;
        float ps = 0.f, pd = 0.f;
        if (grow < NN) {
#pragma unroll
            for (int j = 0; j < 5; j++) {
                int c = tx * 5 + j;
                float v = acc[half][j];
                g_h2[(size_t)grow * C2 + c] = v;
                ps += v * s_as[c];
                pd += v * s_ad[c];
            }
        }
#pragma unroll
        for (int off = 4; off >= 1; off >>= 1) {
            ps += __shfl_xor_sync(0xffffffffu, ps, off);
            pd += __shfl_xor_sync(0xffffffffu, pd, off);
        }
        if (tx == 0 && grow < NN) { g_als2[grow] = ps; g_ald2[grow] = pd; }
    }
}

// =====================================================================
// agg2: warp per dst, fast path deg<=32; fused +b2 and log_softmax
// =====================================================================
__global__ __launch_bounds__(256) void k_agg2(const float* __restrict__ b2,
                                              float* __restrict__ out) {
    const int tid  = threadIdx.x;
    const int wid  = tid >> 5;
    const int lane = tid & 31;
    const int d    = blockIdx.x * 8 + wid;

    const int beg = g_rowptr[d];
    const int end = g_rowptr[d + 1];
    const int deg = end - beg;
    const float ald = g_ald2[d];

    const int c0 = lane, c1 = lane + 32;
    float acc0 = 0.f, acc1 = 0.f;

    if (deg <= 32) {
        int k = beg + lane;
        bool act = k < end;
        int s = act ? g_col[k] : 0;
        float e = act ? lrelu(g_als2[s] + ald) : -1e30f;
        float m = e;
#pragma unroll
        for (int off = 16; off >= 1; off >>= 1)
            m = fmaxf(m, __shfl_xor_sync(0xffffffffu, m, off));
        float p = act ? __expf(e - m) : 0.f;
        float den = p;
#pragma unroll
        for (int off = 16; off >= 1; off >>= 1)
            den += __shfl_xor_sync(0xffffffffu, den, off);
        float alpha = p / den;

#pragma unroll 4
        for (int j = 0; j < deg; j++) {
            int sj  = __shfl_sync(0xffffffffu, s, j);
            float a = __shfl_sync(0xffffffffu, alpha, j);
            const float* hp = &g_h2[(size_t)sj * C2];
            acc0 = fmaf(__ldg(hp + c0), a, acc0);
            if (lane < 8) acc1 = fmaf(__ldg(hp + c1), a, acc1);
        }
    } else {
        float m = -1e30f;
        for (int k = beg + lane; k < end; k += 32)
            m = fmaxf(m, lrelu(g_als2[g_col[k]] + ald));
#pragma unroll
        for (int off = 16; off >= 1; off >>= 1)
            m = fmaxf(m, __shfl_xor_sync(0xffffffffu, m, off));

        float den = 0.f;
        for (int k = beg + lane; k < end; k += 32)
            den += __expf(lrelu(g_als2[g_col[k]] + ald) - m);
#pragma unroll
        for (int off = 16; off >= 1; off >>= 1)
            den += __shfl_xor_sync(0xffffffffu, den, off);
        const float inv = 1.f / den;

        for (int base = beg; base < end; base += 32) {
            int k = base + lane;
            int s = 0;
            float alpha = 0.f;
            if (k < end) {
                s = g_col[k];
                alpha = __expf(lrelu(g_als2[s] + ald) - m) * inv;
            }
            int cnt = min(32, end - base);
#pragma unroll 4
            for (int j = 0; j < cnt; j++) {
                int sj  = __shfl_sync(0xffffffffu, s, j);
                float a = __shfl_sync(0xffffffffu, alpha, j);
                const float* hp = &g_h2[(size_t)sj * C2];
                acc0 = fmaf(__ldg(hp + c0), a, acc0);
                if (lane < 8) acc1 = fmaf(__ldg(hp + c1), a, acc1);
            }
        }
    }
    float v0 = acc0 + __ldg(b2 + c0);
    float v1 = (lane < 8) ? acc1 + __ldg(b2 + c1) : -1e30f;
    float mm = fmaxf(v0, v1);
#pragma unroll
    for (int off = 16; off >= 1; off >>= 1)
        mm = fmaxf(mm, __shfl_xor_sync(0xffffffffu, mm, off));
    float se = __expf(v0 - mm) + ((lane < 8) ? __expf(v1 - mm) : 0.f);
#pragma unroll
    for (int off = 16; off >= 1; off >>= 1)
        se += __shfl_xor_sync(0xffffffffu, se, off);
    float lse = logf(se) + mm;
    out[(size_t)d * C2 + c0] = v0 - lse;
    if (lane < 8) out[(size_t)d * C2 + c1] = v1 - lse;
}

// =====================================================================
extern "C" void kernel_launch(void* const* d_in, const int* in_sizes, int n_in,
                              void* d_out, int out_size) {
    const float* x    = (const float*)d_in[0];
    const int*   ei   = (const int*)  d_in[1];
    const float* W1   = (const float*)d_in[2];
    const float* as1  = (const float*)d_in[3];
    const float* ad1  = (const float*)d_in[4];
    const float* b1   = (const float*)d_in[5];
    const float* W2   = (const float*)d_in[6];
    const float* as2  = (const float*)d_in[7];
    const float* ad2  = (const float*)d_in[8];
    const float* b2   = (const float*)d_in[9];
    float* out = (float*)d_out;

    k_prepw   <<<(FIN * C1 + 255) / 256, 256>>>(W1);
    k_initcnt <<<(NN + 255) / 256, 256>>>();
    k_hist    <<<(EE + 255) / 256, 256>>>(ei);
    k_gemm1_tc<<<(NN + 127) / 128, 256>>>(x, as1, ad1);
    k_scanA   <<<NBLK, 1024>>>();
    k_scanB   <<<1, 1>>>();
    k_scanC   <<<NBLK, 1024>>>();
    k_scatter <<<(EE + NN + 255) / 256, 256>>>(ei);
    k_agg1    <<<NN / 8, 256>>>();
    k_gemm2   <<<(NN + 63) / 64, 256>>>(b1, W2, as2, ad2);
    k_agg2    <<<NN / 8, 256>>>(b2, out);
}

// round 9
// speedup vs baseline: 1.0788x; 1.0788x over previous
#include <cuda_runtime.h>
#include <cuda_bf16.h>
#include <math.h>
#include <stdint.h>

// ---------------- problem constants (fixed instance) ----------------
#define NN   100000
#define FIN  512
#define C1   64          // heads1*out1 = 8*8
#define H1   8
#define EE   1600000
#define ET   (EE + NN)   // edges + self loops
#define C2   40
#define NEG  0.2f
#define NBLK 98          // scan blocks: ceil(NN/1024)

// ---------------- static device scratch (no allocs allowed) ----------------
__device__ float g_h1[NN * C1];
__device__ float g_als1[NN * H1];
__device__ float g_ald1[NN * H1];
__device__ float g_out1[NN * C1];
__device__ float g_h2[NN * C2];
__device__ float g_als2[NN];
__device__ float g_ald2[NN];
__device__ int   g_cnt[NN];
__device__ int   g_rowptr[NN + 1];
__device__ int   g_cursor[NN];
__device__ int   g_col[ET];
__device__ int   g_blksum[NBLK];
__device__ int   g_blkoff[NBLK];
__device__ __nv_bfloat16 g_W1hT[C1 * FIN];   // [n][k] transposed hi
__device__ __nv_bfloat16 g_W1lT[C1 * FIN];   // [n][k] transposed lo

__device__ __forceinline__ float lrelu(float x) { return x > 0.f ? x : NEG * x; }

__device__ __forceinline__ uint32_t smem_u32(const void* p) {
    return (uint32_t)__cvta_generic_to_shared(p);
}
// pack two f32 -> bf16x2 word (lo half = a, hi half = b)
__device__ __forceinline__ uint32_t bf16x2(float a, float b) {
    uint32_t r;
    asm("cvt.rn.bf16x2.f32 %0, %1, %2;" : "=r"(r) : "f"(b), "f"(a));
    return r;
}

#define LDSM4(r0, r1, r2, r3, addr)                                            \
    asm volatile("ldmatrix.sync.aligned.m8n8.x4.shared.b16 {%0,%1,%2,%3},[%4];"\
                 : "=r"(r0), "=r"(r1), "=r"(r2), "=r"(r3) : "r"(addr))

#define MMA_BF16(d, a, b0, b1)                                                 \
    asm volatile(                                                              \
        "mma.sync.aligned.m16n8k16.row.col.f32.bf16.bf16.f32 "                 \
        "{%0,%1,%2,%3},{%4,%5,%6,%7},{%8,%9},{%0,%1,%2,%3};"                   \
        : "+f"(d[0]), "+f"(d[1]), "+f"(d[2]), "+f"(d[3])                       \
        : "r"(a[0]), "r"(a[1]), "r"(a[2]), "r"(a[3]), "r"(b0), "r"(b1))

#define CP_ASYNC16(dst, src)                                                   \
    asm volatile("cp.async.ca.shared.global [%0], [%1], 16;" ::                \
                 "r"(dst), "l"(src))

// =====================================================================
// prep: split W1 into bf16 hi/lo, transposed to [n][k]
// =====================================================================
__global__ void k_prepw(const float* __restrict__ W) {
    int i = blockIdx.x * blockDim.x + threadIdx.x;
    if (i < FIN * C1) {
        int k = i >> 6, n = i & 63;
        float w = W[i];
        __nv_bfloat16 hi = __float2bfloat16(w);
        __nv_bfloat16 lo = __float2bfloat16(w - __bfloat162float(hi));
        g_W1hT[n * FIN + k] = hi;
        g_W1lT[n * FIN + k] = lo;
    }
}

// =====================================================================
// GEMM1: bf16 split-MMA, M=128 x N=64 tile, KC=32, 8 warps (m16 each).
// A: GMEM -> registers directly (no A smem). B: cp.async double-buffered.
// Fused logits1 in epilogue.
// =====================================================================
__global__ __launch_bounds__(256, 3) void k_gemm1_tc(const float* __restrict__ x,
                                                     const float* __restrict__ as1,
                                                     const float* __restrict__ ad1) {
    __shared__ uint32_t Bh[2][64][20];    // [buf][n][kwords], 16 words used, 20 stride
    __shared__ uint32_t Bl[2][64][20];

    const int tid  = threadIdx.x;
    const int warp = tid >> 5;
    const int lane = tid & 31;
    const int r0   = blockIdx.x * 128;
    const int mrow = warp * 16;
    const int q    = lane & 3;
    const int g4   = lane >> 2;

    // ---- A direct-load row pointers (clamped) ----
    int row0 = r0 + mrow + g4;      if (row0 >= NN) row0 = NN - 1;
    int row1 = r0 + mrow + g4 + 8;  if (row1 >= NN) row1 = NN - 1;
    const float* xp0 = x + (size_t)row0 * FIN;
    const float* xp1 = x + (size_t)row1 * FIN;

    // ---- B cp.async mapping: thread -> (n, 8 k) ----
    const int bn = tid >> 2;
    const int bw = tid & 3;
    const __nv_bfloat16* whp = g_W1hT + bn * FIN + bw * 8;
    const __nv_bfloat16* wlp = g_W1lT + bn * FIN + bw * 8;

    // ---- B ldmatrix lane offsets (validated in round 4) ----
    const int bmat = lane >> 3;
    uint32_t bOff[4];
#pragma unroll
    for (int p = 0; p < 4; p++) {
        int n = p * 16 + (bmat >> 1) * 8 + (lane & 7);
        bOff[p] = (uint32_t)((n * 20 + (bmat & 1) * 4) * 4);   // bytes
    }
    const uint32_t bBaseH0 = smem_u32(&Bh[0][0][0]);
    const uint32_t bBaseL0 = smem_u32(&Bl[0][0][0]);
    const uint32_t bufStride = (uint32_t)(64 * 20 * 4);

    float acc[8][4];
#pragma unroll
    for (int nb = 0; nb < 8; nb++)
#pragma unroll
        for (int i = 0; i < 4; i++) acc[nb][i] = 0.f;

    // ---- prologue: A chunk 0 regs, cp.async B tile 0 ----
    float2 va0 = *(const float2*)(xp0 + 2 * q);
    float2 va1 = *(const float2*)(xp1 + 2 * q);
    float2 va2 = *(const float2*)(xp0 + 2 * q + 8);
    float2 va3 = *(const float2*)(xp1 + 2 * q + 8);
    {
        uint32_t dh = smem_u32(&Bh[0][bn][bw * 4]);
        uint32_t dl = smem_u32(&Bl[0][bn][bw * 4]);
        CP_ASYNC16(dh, whp);
        CP_ASYNC16(dl, wlp);
        asm volatile("cp.async.commit_group;");
    }

    for (int t = 0; t < 16; t++) {
        if (t < 15) {
            int nb2 = (t + 1) & 1;
            uint32_t dh = smem_u32(&Bh[nb2][bn][bw * 4]);
            uint32_t dl = smem_u32(&Bl[nb2][bn][bw * 4]);
            CP_ASYNC16(dh, whp + (t + 1) * 32);
            CP_ASYNC16(dl, wlp + (t + 1) * 32);
            asm volatile("cp.async.commit_group;");
            asm volatile("cp.async.wait_group 1;");
        } else {
            asm volatile("cp.async.wait_group 0;");
        }
        __syncthreads();

        const uint32_t bh = bBaseH0 + (t & 1) * bufStride;
        const uint32_t bl = bBaseL0 + (t & 1) * bufStride;

#pragma unroll
        for (int s = 0; s < 2; s++) {
            const int c = 2 * t + s;
            // prefetch next A chunk while doing this chunk's MMAs
            float2 w0, w1, w2, w3;
            if (c < 31) {
                int col = (c + 1) * 16 + 2 * q;
                w0 = *(const float2*)(xp0 + col);
                w1 = *(const float2*)(xp1 + col);
                w2 = *(const float2*)(xp0 + col + 8);
                w3 = *(const float2*)(xp1 + col + 8);
            }
            // convert current chunk to hi/lo fragments
            uint32_t ah[4], al[4];
            ah[0] = bf16x2(va0.x, va0.y);
            ah[1] = bf16x2(va1.x, va1.y);
            ah[2] = bf16x2(va2.x, va2.y);
            ah[3] = bf16x2(va3.x, va3.y);
            al[0] = bf16x2(va0.x - __uint_as_float(ah[0] << 16), va0.y - __uint_as_float(ah[0] & 0xffff0000u));
            al[1] = bf16x2(va1.x - __uint_as_float(ah[1] << 16), va1.y - __uint_as_float(ah[1] & 0xffff0000u));
            al[2] = bf16x2(va2.x - __uint_as_float(ah[2] << 16), va2.y - __uint_as_float(ah[2] & 0xffff0000u));
            al[3] = bf16x2(va3.x - __uint_as_float(ah[3] << 16), va3.y - __uint_as_float(ah[3] & 0xffff0000u));
#pragma unroll
            for (int p = 0; p < 4; p++) {
                uint32_t h0, h1, h2, h3, q0, q1, q2, q3;
                LDSM4(h0, h1, h2, h3, bh + bOff[p] + s * 32);
                LDSM4(q0, q1, q2, q3, bl + bOff[p] + s * 32);
                MMA_BF16(acc[2 * p],     ah, h0, h1);
                MMA_BF16(acc[2 * p],     al, h0, h1);
                MMA_BF16(acc[2 * p],     ah, q0, q1);
                MMA_BF16(acc[2 * p + 1], ah, h2, h3);
                MMA_BF16(acc[2 * p + 1], al, h2, h3);
                MMA_BF16(acc[2 * p + 1], ah, q2, q3);
            }
            va0 = w0; va1 = w1; va2 = w2; va3 = w3;
        }
        __syncthreads();
    }

    // ---- epilogue: store h1 + fused per-head logits ----
    float sv[16], dv[16];
#pragma unroll
    for (int nb = 0; nb < 8; nb++) {
        sv[nb * 2]     = __ldg(as1 + nb * 8 + 2 * q);
        sv[nb * 2 + 1] = __ldg(as1 + nb * 8 + 2 * q + 1);
        dv[nb * 2]     = __ldg(ad1 + nb * 8 + 2 * q);
        dv[nb * 2 + 1] = __ldg(ad1 + nb * 8 + 2 * q + 1);
    }
#pragma unroll
    for (int half = 0; half < 2; half++) {
        int grw = r0 + mrow + g4 + half * 8;
        float hs[8], hd[8];
#pragma unroll
        for (int nb = 0; nb < 8; nb++) {
            float c0 = acc[nb][half * 2];
            float c1 = acc[nb][half * 2 + 1];
            hs[nb] = c0 * sv[nb * 2] + c1 * sv[nb * 2 + 1];
            hd[nb] = c0 * dv[nb * 2] + c1 * dv[nb * 2 + 1];
            if (grw < NN) {
                *(float2*)&g_h1[(size_t)grw * C1 + nb * 8 + 2 * q] = make_float2(c0, c1);
            }
        }
#pragma unroll
        for (int off = 1; off <= 2; off <<= 1) {
#pragma unroll
            for (int nb = 0; nb < 8; nb++) {
                hs[nb] += __shfl_xor_sync(0xffffffffu, hs[nb], off);
                hd[nb] += __shfl_xor_sync(0xffffffffu, hd[nb], off);
            }
        }
        if (q == 0 && grw < NN) {
            *(float4*)&g_als1[grw * H1]     = make_float4(hs[0], hs[1], hs[2], hs[3]);
            *(float4*)&g_als1[grw * H1 + 4] = make_float4(hs[4], hs[5], hs[6], hs[7]);
            *(float4*)&g_ald1[grw * H1]     = make_float4(hd[0], hd[1], hd[2], hd[3]);
            *(float4*)&g_ald1[grw * H1 + 4] = make_float4(hd[4], hd[5], hd[6], hd[7]);
        }
    }
}

// =====================================================================
// CSR build
// =====================================================================
__global__ void k_initcnt() {
    int i = blockIdx.x * blockDim.x + threadIdx.x;
    if (i < NN) g_cnt[i] = 1;
}

__global__ void k_hist(const int* __restrict__ ei) {
    int e = blockIdx.x * blockDim.x + threadIdx.x;
    if (e < EE) atomicAdd(&g_cnt[ei[EE + e]], 1);
}

__global__ __launch_bounds__(1024) void k_scanA() {
    __shared__ int wsum[32];
    const int t    = threadIdx.x;
    const int lane = t & 31;
    const int warp = t >> 5;
    const int idx  = blockIdx.x * 1024 + t;
    int v = (idx < NN) ? g_cnt[idx] : 0;
    int s = v;
#pragma unroll
    for (int off = 1; off < 32; off <<= 1) {
        int n = __shfl_up_sync(0xffffffffu, s, off);
        if (lane >= off) s += n;
    }
    if (lane == 31) wsum[warp] = s;
    __syncthreads();
    if (warp == 0) {
        int ws = wsum[lane];
#pragma unroll
        for (int off = 1; off < 32; off <<= 1) {
            int n = __shfl_up_sync(0xffffffffu, ws, off);
            if (lane >= off) ws += n;
        }
        wsum[lane] = ws;
    }
    __syncthreads();
    int incl = s + (warp > 0 ? wsum[warp - 1] : 0);
    if (idx < NN) g_rowptr[idx] = incl - v;
    if (t == 1023) g_blksum[blockIdx.x] = incl;
}

__global__ void k_scanB() {
    int run = 0;
    for (int b = 0; b < NBLK; b++) {
        g_blkoff[b] = run;
        run += g_blksum[b];
    }
    g_rowptr[NN] = run;
}

__global__ __launch_bounds__(1024) void k_scanC() {
    int idx = blockIdx.x * 1024 + threadIdx.x;
    if (idx < NN) {
        int r = g_rowptr[idx] + g_blkoff[idx >> 10];
        g_rowptr[idx] = r;
        g_cursor[idx] = r;
    }
}

__global__ void k_scatter(const int* __restrict__ ei) {
    int i = blockIdx.x * blockDim.x + threadIdx.x;
    if (i >= EE + NN) return;
    int s, d;
    if (i < EE) { s = ei[i]; d = ei[EE + i]; }
    else        { s = i - EE; d = s; }
    int p = atomicAdd(&g_cursor[d], 1);
    g_col[p] = s;
}

// =====================================================================
// agg1: warp per dst. Fast path for degree<=32.
// =====================================================================
__global__ __launch_bounds__(256) void k_agg1() {
    __shared__ float s_alpha[8][32 * 8];
    const int tid  = threadIdx.x;
    const int wid  = tid >> 5;
    const int lane = tid & 31;
    const int d    = blockIdx.x * 8 + wid;

    const int beg = g_rowptr[d];
    const int end = g_rowptr[d + 1];
    const int deg = end - beg;

    float4 ad0 = *(const float4*)&g_ald1[d * H1];
    float4 ad1 = *(const float4*)&g_ald1[d * H1 + 4];
    float ald[H1] = {ad0.x, ad0.y, ad0.z, ad0.w, ad1.x, ad1.y, ad1.z, ad1.w};

    float* sa = s_alpha[wid];
    const int c0 = lane, c1 = lane + 32;
    const int h0 = lane >> 3;
    float acc0 = 0.f, acc1 = 0.f;

    if (deg <= 32) {
        int k = beg + lane;
        bool act = k < end;
        int s = act ? g_col[k] : 0;
        float e[H1];
        if (act) {
            float4 a0 = *(const float4*)&g_als1[s * H1];
            float4 a1 = *(const float4*)&g_als1[s * H1 + 4];
            float av[H1] = {a0.x, a0.y, a0.z, a0.w, a1.x, a1.y, a1.z, a1.w};
#pragma unroll
            for (int h = 0; h < H1; h++) e[h] = lrelu(av[h] + ald[h]);
        } else {
#pragma unroll
            for (int h = 0; h < H1; h++) e[h] = -1e30f;
        }
        float m[H1], p[H1], den[H1];
#pragma unroll
        for (int h = 0; h < H1; h++) m[h] = e[h];
#pragma unroll
        for (int h = 0; h < H1; h++)
#pragma unroll
            for (int off = 16; off >= 1; off >>= 1)
                m[h] = fmaxf(m[h], __shfl_xor_sync(0xffffffffu, m[h], off));
#pragma unroll
        for (int h = 0; h < H1; h++) { p[h] = act ? __expf(e[h] - m[h]) : 0.f; den[h] = p[h]; }
#pragma unroll
        for (int h = 0; h < H1; h++)
#pragma unroll
            for (int off = 16; off >= 1; off >>= 1)
                den[h] += __shfl_xor_sync(0xffffffffu, den[h], off);
#pragma unroll
        for (int h = 0; h < H1; h++) p[h] *= (1.f / den[h]);

        *(float4*)&sa[lane * 8]     = make_float4(p[0], p[1], p[2], p[3]);
        *(float4*)&sa[lane * 8 + 4] = make_float4(p[4], p[5], p[6], p[7]);
        __syncwarp();
        for (int j = 0; j < deg; j++) {
            int sj = __shfl_sync(0xffffffffu, s, j);
            float a0 = sa[j * 8 + h0];
            float a1 = sa[j * 8 + h0 + 4];
            const float* hp = &g_h1[(size_t)sj * C1];
            acc0 = fmaf(__ldg(hp + c0), a0, acc0);
            acc1 = fmaf(__ldg(hp + c1), a1, acc1);
        }
    } else {
        float m[H1];
#pragma unroll
        for (int h = 0; h < H1; h++) m[h] = -1e30f;
        for (int k = beg + lane; k < end; k += 32) {
            int s = g_col[k];
            float4 a0 = *(const float4*)&g_als1[s * H1];
            float4 a1 = *(const float4*)&g_als1[s * H1 + 4];
            float av[H1] = {a0.x, a0.y, a0.z, a0.w, a1.x, a1.y, a1.z, a1.w};
#pragma unroll
            for (int h = 0; h < H1; h++) m[h] = fmaxf(m[h], lrelu(av[h] + ald[h]));
        }
#pragma unroll
        for (int h = 0; h < H1; h++)
#pragma unroll
            for (int off = 16; off >= 1; off >>= 1)
                m[h] = fmaxf(m[h], __shfl_xor_sync(0xffffffffu, m[h], off));

        float den[H1];
#pragma unroll
        for (int h = 0; h < H1; h++) den[h] = 0.f;
        for (int k = beg + lane; k < end; k += 32) {
            int s = g_col[k];
            float4 a0 = *(const float4*)&g_als1[s * H1];
            float4 a1 = *(const float4*)&g_als1[s * H1 + 4];
            float av[H1] = {a0.x, a0.y, a0.z, a0.w, a1.x, a1.y, a1.z, a1.w};
#pragma unroll
            for (int h = 0; h < H1; h++) den[h] += __expf(lrelu(av[h] + ald[h]) - m[h]);
        }
#pragma unroll
        for (int h = 0; h < H1; h++)
#pragma unroll
            for (int off = 16; off >= 1; off >>= 1)
                den[h] += __shfl_xor_sync(0xffffffffu, den[h], off);
        float inv[H1];
#pragma unroll
        for (int h = 0; h < H1; h++) inv[h] = 1.f / den[h];

        for (int base = beg; base < end; base += 32) {
            int k = base + lane;
            int s = 0;
            float al[H1];
#pragma unroll
            for (int h = 0; h < H1; h++) al[h] = 0.f;
            if (k < end) {
                s = g_col[k];
                float4 a0 = *(const float4*)&g_als1[s * H1];
                float4 a1 = *(const float4*)&g_als1[s * H1 + 4];
                float av[H1] = {a0.x, a0.y, a0.z, a0.w, a1.x, a1.y, a1.z, a1.w};
#pragma unroll
                for (int h = 0; h < H1; h++)
                    al[h] = __expf(lrelu(av[h] + ald[h]) - m[h]) * inv[h];
            }
            *(float4*)&sa[lane * 8]     = make_float4(al[0], al[1], al[2], al[3]);
            *(float4*)&sa[lane * 8 + 4] = make_float4(al[4], al[5], al[6], al[7]);
            __syncwarp();
            int cnt = min(32, end - base);
            for (int j = 0; j < cnt; j++) {
                int sj = __shfl_sync(0xffffffffu, s, j);
                float a0 = sa[j * 8 + h0];
                float a1 = sa[j * 8 + h0 + 4];
                const float* hp = &g_h1[(size_t)sj * C1];
                acc0 = fmaf(__ldg(hp + c0), a0, acc0);
                acc1 = fmaf(__ldg(hp + c1), a1, acc1);
            }
            __syncwarp();
        }
    }
    g_out1[(size_t)d * C1 + c0] = acc0;
    g_out1[(size_t)d * C1 + c1] = acc1;
}

// =====================================================================
// GEMM2 fused: h2 = lrelu(out1 + b1) @ W2 ; also logits2
// =====================================================================
__global__ __launch_bounds__(256) void k_gemm2(const float* __restrict__ b1,
                                               const float* __restrict__ W2,
                                               const float* __restrict__ att_s,
                                               const float* __restrict__ att_d) {
    __shared__ float As[64][65];
    __shared__ float Ws[64][C2];
    __shared__ float sb1[64], s_as[C2], s_ad[C2];
    const int tid = threadIdx.x;
    if (tid < 64) sb1[tid] = b1[tid];
    if (tid < C2) { s_as[tid] = att_s[tid]; s_ad[tid] = att_d[tid]; }
    __syncthreads();

    const int r0 = blockIdx.x * 64;
    for (int i = tid; i < 64 * C2; i += 256) Ws[i / C2][i % C2] = W2[i];
#pragma unroll
    for (int it = 0; it < 4; it++) {
        int idx  = tid + it * 256;
        int row  = idx >> 4;
        int c4   = (idx & 15) * 4;
        int grow = r0 + row;
        if (grow >= NN) grow = NN - 1;
        float4 v = *(const float4*)&g_out1[(size_t)grow * C1 + c4];
        As[row][c4 + 0] = lrelu(v.x + sb1[c4 + 0]);
        As[row][c4 + 1] = lrelu(v.y + sb1[c4 + 1]);
        As[row][c4 + 2] = lrelu(v.z + sb1[c4 + 2]);
        As[row][c4 + 3] = lrelu(v.w + sb1[c4 + 3]);
    }
    __syncthreads();

    const int tx = tid & 7;
    const int tn = tid >> 3;
    float acc[2][5];
#pragma unroll
    for (int h = 0; h < 2; h++)
#pragma unroll
        for (int j = 0; j < 5; j++) acc[h][j] = 0.f;

#pragma unroll 4
    for (int k = 0; k < 64; k++) {
        float a0 = As[tn][k];
        float a1 = As[tn + 32][k];
#pragma unroll
        for (int j = 0; j < 5; j++) {
            float w = Ws[k][tx * 5 + j];
            acc[0][j] = fmaf(a0, w, acc[0][j]);
            acc[1][j] = fmaf(a1, w, acc[1][j]);
        }
    }
#pragma unroll
    for (int half = 0; half < 2; half++) {
        int grow = r0 + tn + half * 32;
        float ps = 0.f, pd = 0.f;
        if (grow < NN) {
#pragma unroll
            for (int j = 0; j < 5; j++) {
                int c = tx * 5 + j;
                float v = acc[half][j];
                g_h2[(size_t)grow * C2 + c] = v;
                ps += v * s_as[c];
                pd += v * s_ad[c];
            }
        }
#pragma unroll
        for (int off = 4; off >= 1; off >>= 1) {
            ps += __shfl_xor_sync(0xffffffffu, ps, off);
            pd += __shfl_xor_sync(0xffffffffu, pd, off);
        }
        if (tx == 0 && grow < NN) { g_als2[grow] = ps; g_ald2[grow] = pd; }
    }
}

// =====================================================================
// agg2: warp per dst, fast path deg<=32; fused +b2 and log_softmax
// =====================================================================
__global__ __launch_bounds__(256) void k_agg2(const float* __restrict__ b2,
                                              float* __restrict__ out) {
    const int tid  = threadIdx.x;
    const int wid  = tid >> 5;
    const int lane = tid & 31;
    const int d    = blockIdx.x * 8 + wid;

    const int beg = g_rowptr[d];
    const int end = g_rowptr[d + 1];
    const int deg = end - beg;
    const float ald = g_ald2[d];

    const int c0 = lane, c1 = lane + 32;
    float acc0 = 0.f, acc1 = 0.f;

    if (deg <= 32) {
        int k = beg + lane;
        bool act = k < end;
        int s = act ? g_col[k] : 0;
        float e = act ? lrelu(g_als2[s] + ald) : -1e30f;
        float m = e;
#pragma unroll
        for (int off = 16; off >= 1; off >>= 1)
            m = fmaxf(m, __shfl_xor_sync(0xffffffffu, m, off));
        float p = act ? __expf(e - m) : 0.f;
        float den = p;
#pragma unroll
        for (int off = 16; off >= 1; off >>= 1)
            den += __shfl_xor_sync(0xffffffffu, den, off);
        float alpha = p / den;

        for (int j = 0; j < deg; j++) {
            int sj  = __shfl_sync(0xffffffffu, s, j);
            float a = __shfl_sync(0xffffffffu, alpha, j);
            const float* hp = &g_h2[(size_t)sj * C2];
            acc0 = fmaf(__ldg(hp + c0), a, acc0);
            if (lane < 8) acc1 = fmaf(__ldg(hp + c1), a, acc1);
        }
    } else {
        float m = -1e30f;
        for (int k = beg + lane; k < end; k += 32)
            m = fmaxf(m, lrelu(g_als2[g_col[k]] + ald));
#pragma unroll
        for (int off = 16; off >= 1; off >>= 1)
            m = fmaxf(m, __shfl_xor_sync(0xffffffffu, m, off));

        float den = 0.f;
        for (int k = beg + lane; k < end; k += 32)
            den += __expf(lrelu(g_als2[g_col[k]] + ald) - m);
#pragma unroll
        for (int off = 16; off >= 1; off >>= 1)
            den += __shfl_xor_sync(0xffffffffu, den, off);
        const float inv = 1.f / den;

        for (int base = beg; base < end; base += 32) {
            int k = base + lane;
            int s = 0;
            float alpha = 0.f;
            if (k < end) {
                s = g_col[k];
                alpha = __expf(lrelu(g_als2[s] + ald) - m) * inv;
            }
            int cnt = min(32, end - base);
            for (int j = 0; j < cnt; j++) {
                int sj  = __shfl_sync(0xffffffffu, s, j);
                float a = __shfl_sync(0xffffffffu, alpha, j);
                const float* hp = &g_h2[(size_t)sj * C2];
                acc0 = fmaf(__ldg(hp + c0), a, acc0);
                if (lane < 8) acc1 = fmaf(__ldg(hp + c1), a, acc1);
            }
        }
    }
    float v0 = acc0 + __ldg(b2 + c0);
    float v1 = (lane < 8) ? acc1 + __ldg(b2 + c1) : -1e30f;
    float mm = fmaxf(v0, v1);
#pragma unroll
    for (int off = 16; off >= 1; off >>= 1)
        mm = fmaxf(mm, __shfl_xor_sync(0xffffffffu, mm, off));
    float se = __expf(v0 - mm) + ((lane < 8) ? __expf(v1 - mm) : 0.f);
#pragma unroll
    for (int off = 16; off >= 1; off >>= 1)
        se += __shfl_xor_sync(0xffffffffu, se, off);
    float lse = logf(se) + mm;
    out[(size_t)d * C2 + c0] = v0 - lse;
    if (lane < 8) out[(size_t)d * C2 + c1] = v1 - lse;
}

// =====================================================================
extern "C" void kernel_launch(void* const* d_in, const int* in_sizes, int n_in,
                              void* d_out, int out_size) {
    const float* x    = (const float*)d_in[0];
    const int*   ei   = (const int*)  d_in[1];
    const float* W1   = (const float*)d_in[2];
    const float* as1  = (const float*)d_in[3];
    const float* ad1  = (const float*)d_in[4];
    const float* b1   = (const float*)d_in[5];
    const float* W2   = (const float*)d_in[6];
    const float* as2  = (const float*)d_in[7];
    const float* ad2  = (const float*)d_in[8];
    const float* b2   = (const float*)d_in[9];
    float* out = (float*)d_out;

    k_prepw   <<<(FIN * C1 + 255) / 256, 256>>>(W1);
    k_initcnt <<<(NN + 255) / 256, 256>>>();
    k_hist    <<<(EE + 255) / 256, 256>>>(ei);
    k_gemm1_tc<<<(NN + 127) / 128, 256>>>(x, as1, ad1);
    k_scanA   <<<NBLK, 1024>>>();
    k_scanB   <<<1, 1>>>();
    k_scanC   <<<NBLK, 1024>>>();
    k_scatter <<<(EE + NN + 255) / 256, 256>>>(ei);
    k_agg1    <<<NN / 8, 256>>>();
    k_gemm2   <<<(NN + 63) / 64, 256>>>(b1, W2, as2, ad2);
    k_agg2    <<<NN / 8, 256>>>(b2, out);
}